// round 15
// baseline (speedup 1.0000x reference)
#include <cuda_runtime.h>
#include <math.h>
#include <stdint.h>

#define FULLMASK 0xffffffffu

#define NCAM  6
#define LWIN  36
#define NHEAD 4
#define DHEAD 32
#define QN    1536
#define KN    384
#define KEEPQ 1152
#define TOPK  96
#define NTQ   55296
#define NTK   13824
#define NTO   9216
#define SCALE 0.17677669529663687f
#define LN_EPS 1e-5f

#define ATTH  384       // 12 warps -> 170-reg budget, 4 rows/warp
#define NW    12
#define TILE  48        // 4 rows per warp

// ---------------- scratch ---------------------------------------------------
__device__ float g_xq[NTQ*128];
__device__ float g_xk[NTK*128];
__device__ float g_xv[NTK*128];
__device__ float g_yq[NTQ*128];
__device__ float g_yk[NTK*128];
__device__ float g_yv[NTK*128];
__device__ float g_sal[NHEAD*LWIN*QN];
__device__ float g_abuf[NHEAD*LWIN*QN*DHEAD];
__device__ float g_abar[NTO*128];

// ---------------- fused LayerNorm for q,k,v (one warp per token) ------------
__global__ __launch_bounds__(256) void ln_all(const float* __restrict__ q,
                                              const float* __restrict__ k,
                                              const float* __restrict__ v,
                                              const float* __restrict__ gq,
                                              const float* __restrict__ bq,
                                              const float* __restrict__ gk,
                                              const float* __restrict__ bk,
                                              const float* __restrict__ gv,
                                              const float* __restrict__ bv)
{
    int w = (blockIdx.x * 256 + threadIdx.x) >> 5;
    int lane = threadIdx.x & 31;
    const float *X, *G, *B;
    float* Y;
    if (w < NTQ) {
        X = q + (size_t)w * 128; Y = g_xq + (size_t)w * 128; G = gq; B = bq;
    } else if (w < NTQ + NTK) {
        int w2 = w - NTQ;
        X = k + (size_t)w2 * 128; Y = g_xk + (size_t)w2 * 128; G = gk; B = bk;
    } else {
        int w2 = w - NTQ - NTK;
        X = v + (size_t)w2 * 128; Y = g_xv + (size_t)w2 * 128; G = gv; B = bv;
    }
    float4 xv = ((const float4*)X)[lane];
    float s  = xv.x + xv.y + xv.z + xv.w;
    float ss = xv.x*xv.x + xv.y*xv.y + xv.z*xv.z + xv.w*xv.w;
    #pragma unroll
    for (int o = 16; o; o >>= 1) {
        s  += __shfl_xor_sync(FULLMASK, s,  o);
        ss += __shfl_xor_sync(FULLMASK, ss, o);
    }
    float mu  = s * (1.f / 128.f);
    float var = ss * (1.f / 128.f) - mu * mu;
    float rs  = rsqrtf(var + LN_EPS);
    float4 gv4 = ((const float4*)G)[lane];
    float4 bv4 = ((const float4*)B)[lane];
    float4 o4;
    o4.x = (xv.x - mu) * rs * gv4.x + bv4.x;
    o4.y = (xv.y - mu) * rs * gv4.y + bv4.y;
    o4.z = (xv.z - mu) * rs * gv4.z + bv4.z;
    o4.w = (xv.w - mu) * rs * gv4.w + bv4.w;
    ((float4*)Y)[lane] = o4;
}

// ---------------- GEMM body (R4-proven) -------------------------------------
#define GCH 32
__device__ __forceinline__ void gemm_body(const float* __restrict__ A,
                                          const float* __restrict__ W,
                                          const float* __restrict__ bias,
                                          const float* __restrict__ skip,
                                          float* __restrict__ C,
                                          size_t mbase, int do_sal, float* smg)
{
    float* As[2] = { smg, smg + 128*33 + 32*128 };
    float* Ws[2] = { smg + 128*33, smg + 2*128*33 + 32*128 };
    int tid = threadIdx.x;
    int ty = tid >> 4, tx = tid & 15;

    float4 pa[4], pw[4];
    #pragma unroll
    for (int r = 0; r < 4; ++r) {
        int i = tid + 256 * r;
        int row = i >> 3, kq = i & 7;
        pa[r] = *(const float4*)(A + (mbase + row) * 128 + kq * 4);
        int kk = i >> 5, c4 = i & 31;
        pw[r] = *(const float4*)(W + (size_t)kk * 128 + c4 * 4);
    }
    #pragma unroll
    for (int r = 0; r < 4; ++r) {
        int i = tid + 256 * r;
        int row = i >> 3, kq = i & 7;
        float* d = &As[0][row * 33 + kq * 4];
        d[0] = pa[r].x; d[1] = pa[r].y; d[2] = pa[r].z; d[3] = pa[r].w;
        int kk = i >> 5, c4 = i & 31;
        *(float4*)&Ws[0][kk * 128 + c4 * 4] = pw[r];
    }
    __syncthreads();

    float acc[8][8];
    #pragma unroll
    for (int i = 0; i < 8; i++)
        #pragma unroll
        for (int j = 0; j < 8; j++) acc[i][j] = 0.f;

    for (int c = 0; c < 4; ++c) {
        int cur = c & 1;
        if (c < 3) {
            #pragma unroll
            for (int r = 0; r < 4; ++r) {
                int i = tid + 256 * r;
                int row = i >> 3, kq = i & 7;
                pa[r] = *(const float4*)(A + (mbase + row) * 128 + (c + 1) * GCH + kq * 4);
                int kk = i >> 5, c4 = i & 31;
                pw[r] = *(const float4*)(W + (size_t)((c + 1) * GCH + kk) * 128 + c4 * 4);
            }
        }
        const float* as = As[cur];
        const float* ws = Ws[cur];
        #pragma unroll 8
        for (int kk = 0; kk < GCH; ++kk) {
            float a[8], bb[8];
            float4 b0 = *(const float4*)&ws[kk * 128 + tx * 8];
            float4 b1 = *(const float4*)&ws[kk * 128 + tx * 8 + 4];
            bb[0]=b0.x; bb[1]=b0.y; bb[2]=b0.z; bb[3]=b0.w;
            bb[4]=b1.x; bb[5]=b1.y; bb[6]=b1.z; bb[7]=b1.w;
            #pragma unroll
            for (int i = 0; i < 8; i++) a[i] = as[(ty * 8 + i) * 33 + kk];
            #pragma unroll
            for (int i = 0; i < 8; i++)
                #pragma unroll
                for (int j = 0; j < 8; j++)
                    acc[i][j] = fmaf(a[i], bb[j], acc[i][j]);
        }
        if (c < 3) {
            int nb = (c + 1) & 1;
            #pragma unroll
            for (int r = 0; r < 4; ++r) {
                int i = tid + 256 * r;
                int row = i >> 3, kq = i & 7;
                float* d = &As[nb][row * 33 + kq * 4];
                d[0] = pa[r].x; d[1] = pa[r].y; d[2] = pa[r].z; d[3] = pa[r].w;
                int kk = i >> 5, c4 = i & 31;
                *(float4*)&Ws[nb][kk * 128 + c4 * 4] = pw[r];
            }
        }
        __syncthreads();
    }

    float4 bi0 = *(const float4*)(bias + tx * 8);
    float4 bi1 = *(const float4*)(bias + tx * 8 + 4);
    #pragma unroll
    for (int i = 0; i < 8; i++) {
        size_t row = mbase + ty * 8 + i;
        float4 o0, o1;
        o0.x = acc[i][0] + bi0.x; o0.y = acc[i][1] + bi0.y;
        o0.z = acc[i][2] + bi0.z; o0.w = acc[i][3] + bi0.w;
        o1.x = acc[i][4] + bi1.x; o1.y = acc[i][5] + bi1.y;
        o1.z = acc[i][6] + bi1.z; o1.w = acc[i][7] + bi1.w;
        if (skip) {
            float4 s0 = *(const float4*)(skip + row * 128 + tx * 8);
            float4 s1 = *(const float4*)(skip + row * 128 + tx * 8 + 4);
            o0.x += s0.x; o0.y += s0.y; o0.z += s0.z; o0.w += s0.w;
            o1.x += s1.x; o1.y += s1.y; o1.z += s1.z; o1.w += s1.w;
        }
        *(float4*)(C + row * 128 + tx * 8)     = o0;
        *(float4*)(C + row * 128 + tx * 8 + 4) = o1;
        if (do_sal) {
            float sv = o0.x*o0.x + o0.y*o0.y + o0.z*o0.z + o0.w*o0.w
                     + o1.x*o1.x + o1.y*o1.y + o1.z*o1.z + o1.w*o1.w;
            sv += __shfl_xor_sync(FULLMASK, sv, 1);
            sv += __shfl_xor_sync(FULLMASK, sv, 2);
            if ((tx & 3) == 0) {
                int h = tx >> 2;
                int r = (int)row;
                int n = r / 9216;
                int rem = r % 9216;
                int l = rem >> 8;
                int w = rem & 255;
                g_sal[(h * LWIN + l) * QN + n * 256 + w] = sv;
            }
        }
    }
}

__global__ __launch_bounds__(256, 2) void gemm_one(const float* __restrict__ A,
                                                   const float* __restrict__ W,
                                                   const float* __restrict__ bias,
                                                   const float* __restrict__ skip,
                                                   float* __restrict__ C, int do_sal)
{
    extern __shared__ float smg[];
    gemm_body(A, W, bias, skip, C, (size_t)blockIdx.x * 128, do_sal, smg);
}

__global__ __launch_bounds__(256, 2) void gemm_kv(const float* __restrict__ Ak,
                                                  const float* __restrict__ Wk,
                                                  const float* __restrict__ bk,
                                                  float* __restrict__ Ck,
                                                  const float* __restrict__ Av,
                                                  const float* __restrict__ Wv,
                                                  const float* __restrict__ bv,
                                                  float* __restrict__ Cv)
{
    extern __shared__ float smg[];
    if (blockIdx.x < NTK / 128)
        gemm_body(Ak, Wk, bk, nullptr, Ck, (size_t)blockIdx.x * 128, 0, smg);
    else
        gemm_body(Av, Wv, bv, nullptr, Cv, (size_t)(blockIdx.x - NTK / 128) * 128, 0, smg);
}

// ---------------- attention -------------------------------------------------
__device__ __forceinline__ float key2float(unsigned k)
{
    return (k & 0x80000000u) ? __uint_as_float(k & 0x7FFFFFFFu)
                             : __uint_as_float(~k);
}

// Exact top-96 thresholds for FOUR rows, interleaved radix with dual early exit.
__device__ __forceinline__ void select4(unsigned kk[4][12], unsigned T[4])
{
    unsigned p[4] = {0,0,0,0};
    int kn[4] = {TOPK,TOPK,TOPK,TOPK};
    int rr[4] = {KN,KN,KN,KN};        // candidates remaining in current prefix
    bool dn[4] = {false,false,false,false};
    unsigned mk = 0;
    #pragma unroll 1
    for (int bit = 31; bit >= 0; --bit) {
        unsigned bm = 1u << bit, nm = mk | bm;
        #pragma unroll
        for (int a = 0; a < 4; ++a) {
            if (!dn[a]) {
                unsigned t = p[a] | bm;
                int c = 0;
                #pragma unroll
                for (int s = 0; s < 12; s++) c += ((kk[a][s] & nm) == t);
                c = (int)__reduce_add_sync(FULLMASK, (unsigned)c);
                if (c >= kn[a]) {
                    p[a] = t; rr[a] = c;
                    if (c == kn[a]) {
                        unsigned mn = 0xFFFFFFFFu;
                        #pragma unroll
                        for (int s = 0; s < 12; s++)
                            if ((kk[a][s] & nm) == p[a]) mn = min(mn, kk[a][s]);
                        T[a] = __reduce_min_sync(FULLMASK, mn);
                        dn[a] = true;
                    }
                } else {
                    kn[a] -= c; rr[a] -= c;
                    if (rr[a] == kn[a]) {       // all remaining candidates selected
                        unsigned mn = 0xFFFFFFFFu;
                        #pragma unroll
                        for (int s = 0; s < 12; s++)
                            if ((kk[a][s] & nm) == p[a]) mn = min(mn, kk[a][s]);
                        T[a] = __reduce_min_sync(FULLMASK, mn);
                        dn[a] = true;
                    }
                }
            }
        }
        mk = nm;
        if (dn[0] && dn[1] && dn[2] && dn[3]) break;
    }
    #pragma unroll
    for (int a = 0; a < 4; ++a) if (!dn[a]) T[a] = p[a];
}

__device__ __forceinline__ void finish_row(const unsigned* key, unsigned T, int lane,
                                           int rowi, int t_global, int hl,
                                           float2* wjs, const float* Vs)
{
    int gq = 0;
    #pragma unroll
    for (int s = 0; s < 12; s++) gq += (key[s] > T);
    int g = (int)__reduce_add_sync(FULLMASK, (unsigned)gq);
    int e_needed = TOPK - g;

    unsigned mx = 0;
    #pragma unroll
    for (int s = 0; s < 12; s++) mx = max(mx, key[s]);
    mx = __reduce_max_sync(FULLMASK, mx);
    float m = key2float(mx);

    unsigned lmask = (1u << lane) - 1u;
    int eqbase = 0;
    int kept[12];
    float p[12];
    #pragma unroll
    for (int s = 0; s < 12; s++) {
        bool eq = (key[s] == T);
        unsigned bal = __ballot_sync(FULLMASK, eq);
        int rank = eqbase + __popc(bal & lmask);
        eqbase += __popc(bal);
        kept[s] = (key[s] > T) || (eq && rank < e_needed);
    }
    float sum = 0.f;
    #pragma unroll
    for (int s = 0; s < 12; s++) {
        p[s] = kept[s] ? __expf(key2float(key[s]) - m) : 0.f;
        sum += p[s];
    }
    #pragma unroll
    for (int o = 16; o; o >>= 1) sum += __shfl_xor_sync(FULLMASK, sum, o);
    float inv = 1.f / sum;
    int posbase = 0;
    #pragma unroll
    for (int s = 0; s < 12; s++) {
        unsigned kb = __ballot_sync(FULLMASK, kept[s] != 0);
        int pos = posbase + __popc(kb & lmask);
        if (kept[s])
            wjs[rowi * TOPK + pos] = make_float2(p[s] * inv,
                                                 __int_as_float(32 * s + lane));
        posbase += __popc(kb);
    }
    __syncwarp(FULLMASK);
    float accd = 0.f;
    #pragma unroll 4
    for (int t = 0; t < TOPK; t++) {
        float2 e = wjs[rowi * TOPK + t];
        accd = fmaf(e.x, Vs[__float_as_int(e.y) * 33 + lane], accd);
    }
    g_abuf[((size_t)hl * QN + t_global) * DHEAD + lane] = accd;
    __syncwarp(FULLMASK);
}

__global__ __launch_bounds__(ATTH, 1) void att_kernel(const float* __restrict__ logit_bias)
{
    extern __shared__ float sm[];
    float*  Ks   = sm;                            // 384*33
    float*  Vs   = Ks + KN * 33;                  // 384*33
    float*  Qs   = Vs + KN * 33;                  // 48*33
    float2* wjs  = (float2*)(Qs + TILE * 33);     // 48*96 float2
    int*    list = (int*)(wjs + TILE * TOPK);     // 1152
    float*  uvec = (float*)(list + KEEPQ);        // 32
    __shared__ int hist[256];
    __shared__ int sh_digit, sh_kneed, sh_g, s_cnt;
    __shared__ int wsum[NW];

    int tid = threadIdx.x, lane = tid & 31, wp = tid >> 5;
    int hl = blockIdx.x;
    int h = hl / LWIN, l = hl % LWIN;
    int xx = l / 6, yy = l % 6;

    float lb = 0.f;
    #pragma unroll
    for (int i = 0; i < 6; i++) lb += logit_bias[i];
    lb *= (1.f / 6.f);

    // K,V head slices for this window
    for (int idx = tid; idx < KN * 32; idx += ATTH) {
        int j = idx >> 5, d = idx & 31;
        int n = j >> 6, rem = j & 63;
        int rk = ((n * 6 + xx) * 6 + yy) * 64 + rem;
        Ks[j * 33 + d] = g_yk[(size_t)rk * 128 + h * 32 + d];
        Vs[j * 33 + d] = g_yv[(size_t)rk * 128 + h * 32 + d];
    }
    if (tid == 0) { s_cnt = 0; sh_g = 0; }
    __syncthreads();

    // uniform vector for pruned rows: mean of first 96 V rows
    if (wp == 0) {
        float s = 0.f;
        #pragma unroll 8
        for (int j = 0; j < TOPK; j++) s += Vs[j * 33 + lane];
        uvec[lane] = s * (1.f / TOPK);
    }

    // -------- fused query pruning: exact top-1152 of 1536 (4 keys/thread) ----
    size_t keepbase = (size_t)hl * QN;
    unsigned keys[4];
    #pragma unroll
    for (int i = 0; i < 4; i++) {
        unsigned u = __float_as_uint(g_sal[keepbase + tid + ATTH * i]);
        keys[i] = (u & 0x80000000u) ? ~u : (u | 0x80000000u);
    }
    unsigned prefix = 0;
    int kneed = KEEPQ;
    for (int pass = 3; pass >= 0; --pass) {
        if (tid < 256) hist[tid] = 0;
        __syncthreads();
        int sh = 8 * pass;
        unsigned hm = (pass == 3) ? 0u : (0xFFFFFFFFu << (sh + 8));
        #pragma unroll
        for (int i = 0; i < 4; i++)
            if ((keys[i] & hm) == (prefix & hm))
                atomicAdd(&hist[(keys[i] >> sh) & 255], 1);
        __syncthreads();
        if (tid == 0) {
            int acc = 0, d = 255;
            for (;;) { acc += hist[d]; if (acc >= kneed || d == 0) break; --d; }
            sh_digit = d;
            sh_kneed = kneed - (acc - hist[d]);
        }
        __syncthreads();
        prefix |= ((unsigned)sh_digit) << sh;
        kneed = sh_kneed;
        __syncthreads();
    }
    unsigned T = prefix;
    {
        int lg = 0;
        #pragma unroll
        for (int i = 0; i < 4; i++) lg += (keys[i] > T);
        atomicAdd(&sh_g, lg);
    }
    __syncthreads();
    int e_needed = KEEPQ - sh_g;
    unsigned lmask = (1u << lane) - 1u;
    int rowbase = 0;
    for (int i = 0; i < 4; i++) {
        bool eq = (keys[i] == T);
        unsigned bal = __ballot_sync(FULLMASK, eq);
        if (lane == 0) wsum[wp] = __popc(bal);
        __syncthreads();
        int wpre = 0;
        for (int ww = 0; ww < wp; ++ww) wpre += wsum[ww];
        int rank = rowbase + wpre + __popc(bal & lmask);
        bool keep = (keys[i] > T) || (eq && rank < e_needed);
        int t = tid + ATTH * i;
        if (keep) {
            int pos = atomicAdd(&s_cnt, 1);
            list[pos] = t;
        } else {
            float4* dst = (float4*)(g_abuf + (keepbase + t) * DHEAD);
            const float4* sv = (const float4*)uvec;
            #pragma unroll
            for (int d = 0; d < 8; d++) dst[d] = sv[d];
        }
        int rt = 0;
        for (int ww = 0; ww < NW; ++ww) rt += wsum[ww];
        rowbase += rt;
        __syncthreads();
    }

    // --------------------------- main attention loop --------------------------
    for (int tile = 0; tile < KEEPQ / TILE; ++tile) {
        // gather 48 kept rows of Q (scaled)
        for (int idx = tid; idx < TILE * 32; idx += ATTH) {
            int qi = idx >> 5, d = idx & 31;
            int t = list[tile * TILE + qi];
            int n = t >> 8, w = t & 255;
            int rq = ((n * 6 + xx) * 6 + yy) * 256 + w;
            Qs[qi * 33 + d] = g_yq[(size_t)rq * 128 + h * 32 + d] * SCALE;
        }
        __syncthreads();

        // logits in registers, 4 rows per warp (K loads amortized over 4 rows)
        float acc[4][12];
        #pragma unroll
        for (int a = 0; a < 4; a++)
            #pragma unroll
            for (int s = 0; s < 12; s++) acc[a][s] = 0.f;
        #pragma unroll 4
        for (int d = 0; d < 32; ++d) {
            float qv[4];
            #pragma unroll
            for (int a = 0; a < 4; a++) qv[a] = Qs[(4 * wp + a) * 33 + d];
            #pragma unroll
            for (int s = 0; s < 12; s++) {
                float kd = Ks[(32 * s + lane) * 33 + d];
                #pragma unroll
                for (int a = 0; a < 4; a++)
                    acc[a][s] = fmaf(qv[a], kd, acc[a][s]);
            }
        }
        unsigned kk[4][12];
        #pragma unroll
        for (int a = 0; a < 4; a++)
            #pragma unroll
            for (int s = 0; s < 12; s++) {
                unsigned u = __float_as_uint(acc[a][s] + lb);
                kk[a][s] = (u & 0x80000000u) ? ~u : (u | 0x80000000u);
            }

        // select (4-row interleaved) + softmax + AV
        unsigned T4[4];
        select4(kk, T4);
        int rowi0 = 4 * wp;
        #pragma unroll 1
        for (int a = 0; a < 4; ++a) {
            int tg = list[tile * TILE + rowi0 + a];
            finish_row(kk[a], T4[a], lane, rowi0 + a, tg, hl, wjs, Vs);
        }
        __syncthreads();
    }
}

// ---------------- mean over cameras into abar -------------------------------
__global__ __launch_bounds__(256) void areduce_kernel()
{
    int idx = blockIdx.x * 256 + threadIdx.x;
    if (idx >= NTO * 128) return;
    int hd = idx & 127, tow = idx >> 7;
    int l = tow >> 8, w = tow & 255;
    int h = hd >> 5, d = hd & 31;
    float s = 0.f;
    #pragma unroll
    for (int n = 0; n < 6; n++)
        s += g_abuf[((size_t)(h * LWIN + l) * QN + n * 256 + w) * DHEAD + d];
    g_abar[idx] = s * (1.f / 6.f);
}

// -------------------------------- launch ------------------------------------
extern "C" void kernel_launch(void* const* d_in, const int* in_sizes, int n_in,
                              void* d_out, int out_size)
{
    const float* q          = (const float*)d_in[0];
    const float* k          = (const float*)d_in[1];
    const float* v          = (const float*)d_in[2];
    const float* skip       = (const float*)d_in[3];
    const float* logit_bias = (const float*)d_in[4];
    const float* g_q        = (const float*)d_in[5];
    const float* b_q        = (const float*)d_in[6];
    const float* g_k        = (const float*)d_in[7];
    const float* b_k        = (const float*)d_in[8];
    const float* g_v        = (const float*)d_in[9];
    const float* b_v        = (const float*)d_in[10];
    const float* Wq         = (const float*)d_in[11];
    const float* bq         = (const float*)d_in[12];
    const float* Wk         = (const float*)d_in[13];
    const float* bk         = (const float*)d_in[14];
    const float* Wv         = (const float*)d_in[15];
    const float* bv         = (const float*)d_in[16];
    const float* Wp         = (const float*)d_in[17];
    const float* bp         = (const float*)d_in[18];
    float* out = (float*)d_out;

    const int GEMM_SMEM = 2 * (128 * 33 + 32 * 128) * 4;   // 66560
    const int ATT_SMEM  = (2 * KN * 33 + TILE * 33 + KEEPQ + 32) * 4
                        + TILE * TOPK * 8;                  // 149312
    cudaFuncSetAttribute(gemm_one,   cudaFuncAttributeMaxDynamicSharedMemorySize, GEMM_SMEM);
    cudaFuncSetAttribute(gemm_kv,    cudaFuncAttributeMaxDynamicSharedMemorySize, GEMM_SMEM);
    cudaFuncSetAttribute(att_kernel, cudaFuncAttributeMaxDynamicSharedMemorySize, ATT_SMEM);

    float *pxq, *pxk, *pxv, *pyq, *pyk, *pyv, *pabar;
    cudaGetSymbolAddress((void**)&pxq, g_xq);
    cudaGetSymbolAddress((void**)&pxk, g_xk);
    cudaGetSymbolAddress((void**)&pxv, g_xv);
    cudaGetSymbolAddress((void**)&pyq, g_yq);
    cudaGetSymbolAddress((void**)&pyk, g_yk);
    cudaGetSymbolAddress((void**)&pyv, g_yv);
    cudaGetSymbolAddress((void**)&pabar, g_abar);

    // idx 0: all three LayerNorms
    ln_all<<<(NTQ + 2 * NTK) / 8, 256>>>(q, k, v, g_q, b_q, g_k, b_k, g_v, b_v);
    // idx 1: k+v projections fused
    gemm_kv<<<2 * (NTK / 128), 256, GEMM_SMEM>>>(pxk, Wk, bk, pyk, pxv, Wv, bv, pyv);
    // idx 2: q projection + saliency epilogue
    gemm_one<<<NTQ / 128, 256, GEMM_SMEM>>>(pxq, Wq, bq, nullptr, pyq, 1);
    // idx 3: attention (prune fused) -- PROFILED SLOT
    att_kernel<<<NHEAD * LWIN, ATTH, ATT_SMEM>>>(logit_bias);
    // idx 4: camera mean
    areduce_kernel<<<(NTO * 128) / 256, 256>>>();
    // idx 5: output projection + skip
    gemm_one<<<NTO / 128, 256, GEMM_SMEM>>>(pabar, Wp, bp, skip, out, 0);
}

// round 16
// speedup vs baseline: 1.1221x; 1.1221x over previous
#include <cuda_runtime.h>
#include <math.h>
#include <stdint.h>

#define FULLMASK 0xffffffffu

#define NCAM  6
#define LWIN  36
#define NHEAD 4
#define DHEAD 32
#define QN    1536
#define KN    384
#define KEEPQ 1152
#define TOPK  96
#define NTQ   55296
#define NTK   13824
#define NTO   9216
#define SCALE 0.17677669529663687f
#define LN_EPS 1e-5f

#define ATTH  512       // 16 warps, 2 rows/warp (R13-proven operating point)
#define NW    16
#define TILE  32
#define KSTR  36        // K/Q smem row stride: 16B-aligned float4, conflict-free

// ---------------- scratch ---------------------------------------------------
__device__ float g_xq[NTQ*128];
__device__ float g_xk[NTK*128];
__device__ float g_xv[NTK*128];
__device__ float g_yq[NTQ*128];
__device__ float g_yk[NTK*128];
__device__ float g_yv[NTK*128];
__device__ float g_sal[NHEAD*LWIN*QN];
__device__ float g_abuf[NHEAD*LWIN*QN*DHEAD];
__device__ float g_abar[NTO*128];

// ---------------- fused LayerNorm for q,k,v (one warp per token) ------------
__global__ __launch_bounds__(256) void ln_all(const float* __restrict__ q,
                                              const float* __restrict__ k,
                                              const float* __restrict__ v,
                                              const float* __restrict__ gq,
                                              const float* __restrict__ bq,
                                              const float* __restrict__ gk,
                                              const float* __restrict__ bk,
                                              const float* __restrict__ gv,
                                              const float* __restrict__ bv)
{
    int w = (blockIdx.x * 256 + threadIdx.x) >> 5;
    int lane = threadIdx.x & 31;
    const float *X, *G, *B;
    float* Y;
    if (w < NTQ) {
        X = q + (size_t)w * 128; Y = g_xq + (size_t)w * 128; G = gq; B = bq;
    } else if (w < NTQ + NTK) {
        int w2 = w - NTQ;
        X = k + (size_t)w2 * 128; Y = g_xk + (size_t)w2 * 128; G = gk; B = bk;
    } else {
        int w2 = w - NTQ - NTK;
        X = v + (size_t)w2 * 128; Y = g_xv + (size_t)w2 * 128; G = gv; B = bv;
    }
    float4 xv = ((const float4*)X)[lane];
    float s  = xv.x + xv.y + xv.z + xv.w;
    float ss = xv.x*xv.x + xv.y*xv.y + xv.z*xv.z + xv.w*xv.w;
    #pragma unroll
    for (int o = 16; o; o >>= 1) {
        s  += __shfl_xor_sync(FULLMASK, s,  o);
        ss += __shfl_xor_sync(FULLMASK, ss, o);
    }
    float mu  = s * (1.f / 128.f);
    float var = ss * (1.f / 128.f) - mu * mu;
    float rs  = rsqrtf(var + LN_EPS);
    float4 gv4 = ((const float4*)G)[lane];
    float4 bv4 = ((const float4*)B)[lane];
    float4 o4;
    o4.x = (xv.x - mu) * rs * gv4.x + bv4.x;
    o4.y = (xv.y - mu) * rs * gv4.y + bv4.y;
    o4.z = (xv.z - mu) * rs * gv4.z + bv4.z;
    o4.w = (xv.w - mu) * rs * gv4.w + bv4.w;
    ((float4*)Y)[lane] = o4;
}

// ---------------- GEMM body (R4-proven) -------------------------------------
#define GCH 32
__device__ __forceinline__ void gemm_body(const float* __restrict__ A,
                                          const float* __restrict__ W,
                                          const float* __restrict__ bias,
                                          const float* __restrict__ skip,
                                          float* __restrict__ C,
                                          size_t mbase, int do_sal, float* smg)
{
    float* As[2] = { smg, smg + 128*33 + 32*128 };
    float* Ws[2] = { smg + 128*33, smg + 2*128*33 + 32*128 };
    int tid = threadIdx.x;
    int ty = tid >> 4, tx = tid & 15;

    float4 pa[4], pw[4];
    #pragma unroll
    for (int r = 0; r < 4; ++r) {
        int i = tid + 256 * r;
        int row = i >> 3, kq = i & 7;
        pa[r] = *(const float4*)(A + (mbase + row) * 128 + kq * 4);
        int kk = i >> 5, c4 = i & 31;
        pw[r] = *(const float4*)(W + (size_t)kk * 128 + c4 * 4);
    }
    #pragma unroll
    for (int r = 0; r < 4; ++r) {
        int i = tid + 256 * r;
        int row = i >> 3, kq = i & 7;
        float* d = &As[0][row * 33 + kq * 4];
        d[0] = pa[r].x; d[1] = pa[r].y; d[2] = pa[r].z; d[3] = pa[r].w;
        int kk = i >> 5, c4 = i & 31;
        *(float4*)&Ws[0][kk * 128 + c4 * 4] = pw[r];
    }
    __syncthreads();

    float acc[8][8];
    #pragma unroll
    for (int i = 0; i < 8; i++)
        #pragma unroll
        for (int j = 0; j < 8; j++) acc[i][j] = 0.f;

    for (int c = 0; c < 4; ++c) {
        int cur = c & 1;
        if (c < 3) {
            #pragma unroll
            for (int r = 0; r < 4; ++r) {
                int i = tid + 256 * r;
                int row = i >> 3, kq = i & 7;
                pa[r] = *(const float4*)(A + (mbase + row) * 128 + (c + 1) * GCH + kq * 4);
                int kk = i >> 5, c4 = i & 31;
                pw[r] = *(const float4*)(W + (size_t)((c + 1) * GCH + kk) * 128 + c4 * 4);
            }
        }
        const float* as = As[cur];
        const float* ws = Ws[cur];
        #pragma unroll 8
        for (int kk = 0; kk < GCH; ++kk) {
            float a[8], bb[8];
            float4 b0 = *(const float4*)&ws[kk * 128 + tx * 8];
            float4 b1 = *(const float4*)&ws[kk * 128 + tx * 8 + 4];
            bb[0]=b0.x; bb[1]=b0.y; bb[2]=b0.z; bb[3]=b0.w;
            bb[4]=b1.x; bb[5]=b1.y; bb[6]=b1.z; bb[7]=b1.w;
            #pragma unroll
            for (int i = 0; i < 8; i++) a[i] = as[(ty * 8 + i) * 33 + kk];
            #pragma unroll
            for (int i = 0; i < 8; i++)
                #pragma unroll
                for (int j = 0; j < 8; j++)
                    acc[i][j] = fmaf(a[i], bb[j], acc[i][j]);
        }
        if (c < 3) {
            int nb = (c + 1) & 1;
            #pragma unroll
            for (int r = 0; r < 4; ++r) {
                int i = tid + 256 * r;
                int row = i >> 3, kq = i & 7;
                float* d = &As[nb][row * 33 + kq * 4];
                d[0] = pa[r].x; d[1] = pa[r].y; d[2] = pa[r].z; d[3] = pa[r].w;
                int kk = i >> 5, c4 = i & 31;
                *(float4*)&Ws[nb][kk * 128 + c4 * 4] = pw[r];
            }
        }
        __syncthreads();
    }

    float4 bi0 = *(const float4*)(bias + tx * 8);
    float4 bi1 = *(const float4*)(bias + tx * 8 + 4);
    #pragma unroll
    for (int i = 0; i < 8; i++) {
        size_t row = mbase + ty * 8 + i;
        float4 o0, o1;
        o0.x = acc[i][0] + bi0.x; o0.y = acc[i][1] + bi0.y;
        o0.z = acc[i][2] + bi0.z; o0.w = acc[i][3] + bi0.w;
        o1.x = acc[i][4] + bi1.x; o1.y = acc[i][5] + bi1.y;
        o1.z = acc[i][6] + bi1.z; o1.w = acc[i][7] + bi1.w;
        if (skip) {
            float4 s0 = *(const float4*)(skip + row * 128 + tx * 8);
            float4 s1 = *(const float4*)(skip + row * 128 + tx * 8 + 4);
            o0.x += s0.x; o0.y += s0.y; o0.z += s0.z; o0.w += s0.w;
            o1.x += s1.x; o1.y += s1.y; o1.z += s1.z; o1.w += s1.w;
        }
        *(float4*)(C + row * 128 + tx * 8)     = o0;
        *(float4*)(C + row * 128 + tx * 8 + 4) = o1;
        if (do_sal) {
            float sv = o0.x*o0.x + o0.y*o0.y + o0.z*o0.z + o0.w*o0.w
                     + o1.x*o1.x + o1.y*o1.y + o1.z*o1.z + o1.w*o1.w;
            sv += __shfl_xor_sync(FULLMASK, sv, 1);
            sv += __shfl_xor_sync(FULLMASK, sv, 2);
            if ((tx & 3) == 0) {
                int h = tx >> 2;
                int r = (int)row;
                int n = r / 9216;
                int rem = r % 9216;
                int l = rem >> 8;
                int w = rem & 255;
                g_sal[(h * LWIN + l) * QN + n * 256 + w] = sv;
            }
        }
    }
}

__global__ __launch_bounds__(256, 2) void gemm_one(const float* __restrict__ A,
                                                   const float* __restrict__ W,
                                                   const float* __restrict__ bias,
                                                   const float* __restrict__ skip,
                                                   float* __restrict__ C, int do_sal)
{
    extern __shared__ float smg[];
    gemm_body(A, W, bias, skip, C, (size_t)blockIdx.x * 128, do_sal, smg);
}

__global__ __launch_bounds__(256, 2) void gemm_kv(const float* __restrict__ Ak,
                                                  const float* __restrict__ Wk,
                                                  const float* __restrict__ bk,
                                                  float* __restrict__ Ck,
                                                  const float* __restrict__ Av,
                                                  const float* __restrict__ Wv,
                                                  const float* __restrict__ bv,
                                                  float* __restrict__ Cv)
{
    extern __shared__ float smg[];
    if (blockIdx.x < NTK / 128)
        gemm_body(Ak, Wk, bk, nullptr, Ck, (size_t)blockIdx.x * 128, 0, smg);
    else
        gemm_body(Av, Wv, bv, nullptr, Cv, (size_t)(blockIdx.x - NTK / 128) * 128, 0, smg);
}

// ---------------- attention -------------------------------------------------
__device__ __forceinline__ float key2float(unsigned k)
{
    return (k & 0x80000000u) ? __uint_as_float(k & 0x7FFFFFFFu)
                             : __uint_as_float(~k);
}

// Exact top-96 thresholds for two rows; interleaved radix, dual early exit.
__device__ __forceinline__ void select2(const unsigned* k0, const unsigned* k1,
                                        unsigned& T0, unsigned& T1)
{
    unsigned p[2] = {0,0};
    int kn[2] = {TOPK,TOPK};
    int rr[2] = {KN,KN};
    bool dn[2] = {false,false};
    const unsigned* kv[2] = {k0, k1};
    unsigned Tt[2];
    unsigned mk = 0;
    #pragma unroll 1
    for (int bit = 31; bit >= 0; --bit) {
        unsigned bm = 1u << bit, nm = mk | bm;
        #pragma unroll
        for (int a = 0; a < 2; ++a) {
            if (!dn[a]) {
                unsigned t = p[a] | bm;
                int c = 0;
                #pragma unroll
                for (int s = 0; s < 12; s++) c += ((kv[a][s] & nm) == t);
                c = (int)__reduce_add_sync(FULLMASK, (unsigned)c);
                if (c >= kn[a]) {
                    p[a] = t; rr[a] = c;
                    if (c == kn[a]) {
                        unsigned mn = 0xFFFFFFFFu;
                        #pragma unroll
                        for (int s = 0; s < 12; s++)
                            if ((kv[a][s] & nm) == p[a]) mn = min(mn, kv[a][s]);
                        Tt[a] = __reduce_min_sync(FULLMASK, mn);
                        dn[a] = true;
                    }
                } else {
                    kn[a] -= c; rr[a] -= c;
                    if (rr[a] == kn[a]) {
                        unsigned mn = 0xFFFFFFFFu;
                        #pragma unroll
                        for (int s = 0; s < 12; s++)
                            if ((kv[a][s] & nm) == p[a]) mn = min(mn, kv[a][s]);
                        Tt[a] = __reduce_min_sync(FULLMASK, mn);
                        dn[a] = true;
                    }
                }
            }
        }
        mk = nm;
        if (dn[0] && dn[1]) break;
    }
    T0 = dn[0] ? Tt[0] : p[0];
    T1 = dn[1] ? Tt[1] : p[1];
}

__device__ __forceinline__ void finish_row(const unsigned* key, unsigned T, int lane,
                                           int rowi, int t_global, int hl,
                                           float2* wjs, const float* Vs)
{
    int gq = 0;
    #pragma unroll
    for (int s = 0; s < 12; s++) gq += (key[s] > T);
    int g = (int)__reduce_add_sync(FULLMASK, (unsigned)gq);
    int e_needed = TOPK - g;

    unsigned mx = 0;
    #pragma unroll
    for (int s = 0; s < 12; s++) mx = max(mx, key[s]);
    mx = __reduce_max_sync(FULLMASK, mx);
    float m = key2float(mx);

    unsigned lmask = (1u << lane) - 1u;
    int eqbase = 0;
    int kept[12];
    float p[12];
    #pragma unroll
    for (int s = 0; s < 12; s++) {
        bool eq = (key[s] == T);
        unsigned bal = __ballot_sync(FULLMASK, eq);
        int rank = eqbase + __popc(bal & lmask);
        eqbase += __popc(bal);
        kept[s] = (key[s] > T) || (eq && rank < e_needed);
    }
    float sum = 0.f;
    #pragma unroll
    for (int s = 0; s < 12; s++) {
        p[s] = kept[s] ? __expf(key2float(key[s]) - m) : 0.f;
        sum += p[s];
    }
    #pragma unroll
    for (int o = 16; o; o >>= 1) sum += __shfl_xor_sync(FULLMASK, sum, o);
    float inv = 1.f / sum;
    int posbase = 0;
    #pragma unroll
    for (int s = 0; s < 12; s++) {
        unsigned kb = __ballot_sync(FULLMASK, kept[s] != 0);
        int pos = posbase + __popc(kb & lmask);
        if (kept[s])
            wjs[rowi * TOPK + pos] = make_float2(p[s] * inv,
                                                 __int_as_float(32 * s + lane));
        posbase += __popc(kb);
    }
    __syncwarp(FULLMASK);
    // AV: two compacted (w,j) pairs per LDS.128; j uniform per iter -> V conflict-free
    float accd = 0.f;
    const float4* wj4 = (const float4*)(wjs + rowi * TOPK);
    #pragma unroll 4
    for (int t = 0; t < TOPK / 2; t++) {
        float4 e = wj4[t];
        accd = fmaf(e.x, Vs[__float_as_int(e.y) * 32 + lane], accd);
        accd = fmaf(e.z, Vs[__float_as_int(e.w) * 32 + lane], accd);
    }
    g_abuf[((size_t)hl * QN + t_global) * DHEAD + lane] = accd;
    __syncwarp(FULLMASK);
}

__global__ __launch_bounds__(ATTH, 1) void att_kernel(const float* __restrict__ logit_bias)
{
    extern __shared__ float sm[];
    float*  Ks   = sm;                            // 384*36 (padded for float4)
    float*  Vs   = Ks + KN * KSTR;                // 384*32 (unpadded; j uniform)
    float*  Qs   = Vs + KN * 32;                  // 32*36
    float2* wjs  = (float2*)(Qs + TILE * KSTR);   // 32*96 float2
    int*    list = (int*)(wjs + TILE * TOPK);     // 1152
    float*  uvec = (float*)(list + KEEPQ);        // 32
    __shared__ int hist[256];
    __shared__ int sh_digit, sh_kneed, sh_g, s_cnt;
    __shared__ int wsum[NW];

    int tid = threadIdx.x, lane = tid & 31, wp = tid >> 5;
    int hl = blockIdx.x;
    int h = hl / LWIN, l = hl % LWIN;
    int xx = l / 6, yy = l % 6;

    float lb = 0.f;
    #pragma unroll
    for (int i = 0; i < 6; i++) lb += logit_bias[i];
    lb *= (1.f / 6.f);

    // K,V head slices for this window
    for (int idx = tid; idx < KN * 32; idx += ATTH) {
        int j = idx >> 5, d = idx & 31;
        int n = j >> 6, rem = j & 63;
        int rk = ((n * 6 + xx) * 6 + yy) * 64 + rem;
        Ks[j * KSTR + d] = g_yk[(size_t)rk * 128 + h * 32 + d];
        Vs[j * 32 + d]   = g_yv[(size_t)rk * 128 + h * 32 + d];
    }
    if (tid == 0) { s_cnt = 0; sh_g = 0; }
    __syncthreads();

    // uniform vector for pruned rows: mean of first 96 V rows
    if (wp == 0) {
        float s = 0.f;
        #pragma unroll 8
        for (int j = 0; j < TOPK; j++) s += Vs[j * 32 + lane];
        uvec[lane] = s * (1.f / TOPK);
    }

    // -------- fused query pruning: exact top-1152 of 1536 (3 keys/thread) ----
    size_t keepbase = (size_t)hl * QN;
    unsigned keys[3];
    #pragma unroll
    for (int i = 0; i < 3; i++) {
        unsigned u = __float_as_uint(g_sal[keepbase + tid + ATTH * i]);
        keys[i] = (u & 0x80000000u) ? ~u : (u | 0x80000000u);
    }
    unsigned prefix = 0;
    int kneed = KEEPQ;
    for (int pass = 3; pass >= 0; --pass) {
        if (tid < 256) hist[tid] = 0;
        __syncthreads();
        int sh = 8 * pass;
        unsigned hm = (pass == 3) ? 0u : (0xFFFFFFFFu << (sh + 8));
        #pragma unroll
        for (int i = 0; i < 3; i++)
            if ((keys[i] & hm) == (prefix & hm))
                atomicAdd(&hist[(keys[i] >> sh) & 255], 1);
        __syncthreads();
        if (tid == 0) {
            int acc = 0, d = 255;
            for (;;) { acc += hist[d]; if (acc >= kneed || d == 0) break; --d; }
            sh_digit = d;
            sh_kneed = kneed - (acc - hist[d]);
        }
        __syncthreads();
        prefix |= ((unsigned)sh_digit) << sh;
        kneed = sh_kneed;
        __syncthreads();
    }
    unsigned T = prefix;
    {
        int lg = 0;
        #pragma unroll
        for (int i = 0; i < 3; i++) lg += (keys[i] > T);
        atomicAdd(&sh_g, lg);
    }
    __syncthreads();
    int e_needed = KEEPQ - sh_g;
    unsigned lmask = (1u << lane) - 1u;
    int rowbase = 0;
    for (int i = 0; i < 3; i++) {
        bool eq = (keys[i] == T);
        unsigned bal = __ballot_sync(FULLMASK, eq);
        if (lane == 0) wsum[wp] = __popc(bal);
        __syncthreads();
        int wpre = 0;
        for (int ww = 0; ww < wp; ++ww) wpre += wsum[ww];
        int rank = rowbase + wpre + __popc(bal & lmask);
        bool keep = (keys[i] > T) || (eq && rank < e_needed);
        int t = tid + ATTH * i;
        if (keep) {
            int pos = atomicAdd(&s_cnt, 1);
            list[pos] = t;
        } else {
            float4* dst = (float4*)(g_abuf + (keepbase + t) * DHEAD);
            const float4* sv = (const float4*)uvec;
            #pragma unroll
            for (int d = 0; d < 8; d++) dst[d] = sv[d];
        }
        int rt = 0;
        for (int ww = 0; ww < NW; ++ww) rt += wsum[ww];
        rowbase += rt;
        __syncthreads();
    }

    // --------------------------- main attention loop --------------------------
    for (int tile = 0; tile < KEEPQ / TILE; ++tile) {
        // gather 32 kept rows of Q (scaled), stride-36
        for (int idx = tid; idx < TILE * 32; idx += ATTH) {
            int qi = idx >> 5, d = idx & 31;
            int t = list[tile * TILE + qi];
            int n = t >> 8, w = t & 255;
            int rq = ((n * 6 + xx) * 6 + yy) * 256 + w;
            Qs[qi * KSTR + d] = g_yq[(size_t)rq * 128 + h * 32 + d] * SCALE;
        }
        __syncthreads();

        // logits: float4 K/Q loads, same fp32 FMA order (d ascending)
        float acc[2][12];
        #pragma unroll
        for (int a = 0; a < 2; a++)
            #pragma unroll
            for (int s = 0; s < 12; s++) acc[a][s] = 0.f;
        #pragma unroll
        for (int d4 = 0; d4 < 8; ++d4) {
            float4 q0 = *(const float4*)&Qs[(2 * wp)     * KSTR + d4 * 4];
            float4 q1 = *(const float4*)&Qs[(2 * wp + 1) * KSTR + d4 * 4];
            #pragma unroll
            for (int s = 0; s < 12; s++) {
                float4 kd = *(const float4*)&Ks[(32 * s + lane) * KSTR + d4 * 4];
                acc[0][s] = fmaf(q0.x, kd.x, acc[0][s]);
                acc[0][s] = fmaf(q0.y, kd.y, acc[0][s]);
                acc[0][s] = fmaf(q0.z, kd.z, acc[0][s]);
                acc[0][s] = fmaf(q0.w, kd.w, acc[0][s]);
                acc[1][s] = fmaf(q1.x, kd.x, acc[1][s]);
                acc[1][s] = fmaf(q1.y, kd.y, acc[1][s]);
                acc[1][s] = fmaf(q1.z, kd.z, acc[1][s]);
                acc[1][s] = fmaf(q1.w, kd.w, acc[1][s]);
            }
        }
        unsigned kk[2][12];
        #pragma unroll
        for (int a = 0; a < 2; a++)
            #pragma unroll
            for (int s = 0; s < 12; s++) {
                unsigned u = __float_as_uint(acc[a][s] + lb);
                kk[a][s] = (u & 0x80000000u) ? ~u : (u | 0x80000000u);
            }

        {
            unsigned T0, T1;
            select2(kk[0], kk[1], T0, T1);
            int rowi0 = 2 * wp;
            int t0 = list[tile * TILE + rowi0];
            int t1 = list[tile * TILE + rowi0 + 1];
            finish_row(kk[0], T0, lane, rowi0,     t0, hl, wjs, Vs);
            finish_row(kk[1], T1, lane, rowi0 + 1, t1, hl, wjs, Vs);
        }
        __syncthreads();
    }
}

// ---------------- mean over cameras into abar -------------------------------
__global__ __launch_bounds__(256) void areduce_kernel()
{
    int idx = blockIdx.x * 256 + threadIdx.x;
    if (idx >= NTO * 128) return;
    int hd = idx & 127, tow = idx >> 7;
    int l = tow >> 8, w = tow & 255;
    int h = hd >> 5, d = hd & 31;
    float s = 0.f;
    #pragma unroll
    for (int n = 0; n < 6; n++)
        s += g_abuf[((size_t)(h * LWIN + l) * QN + n * 256 + w) * DHEAD + d];
    g_abar[idx] = s * (1.f / 6.f);
}

// -------------------------------- launch ------------------------------------
extern "C" void kernel_launch(void* const* d_in, const int* in_sizes, int n_in,
                              void* d_out, int out_size)
{
    const float* q          = (const float*)d_in[0];
    const float* k          = (const float*)d_in[1];
    const float* v          = (const float*)d_in[2];
    const float* skip       = (const float*)d_in[3];
    const float* logit_bias = (const float*)d_in[4];
    const float* g_q        = (const float*)d_in[5];
    const float* b_q        = (const float*)d_in[6];
    const float* g_k        = (const float*)d_in[7];
    const float* b_k        = (const float*)d_in[8];
    const float* g_v        = (const float*)d_in[9];
    const float* b_v        = (const float*)d_in[10];
    const float* Wq         = (const float*)d_in[11];
    const float* bq         = (const float*)d_in[12];
    const float* Wk         = (const float*)d_in[13];
    const float* bk         = (const float*)d_in[14];
    const float* Wv         = (const float*)d_in[15];
    const float* bv         = (const float*)d_in[16];
    const float* Wp         = (const float*)d_in[17];
    const float* bp         = (const float*)d_in[18];
    float* out = (float*)d_out;

    const int GEMM_SMEM = 2 * (128 * 33 + 32 * 128) * 4;   // 66560
    const int ATT_SMEM  = (KN * KSTR + KN * 32 + TILE * KSTR + KEEPQ + 32) * 4
                        + TILE * TOPK * 8;                  // ~134 KB
    cudaFuncSetAttribute(gemm_one,   cudaFuncAttributeMaxDynamicSharedMemorySize, GEMM_SMEM);
    cudaFuncSetAttribute(gemm_kv,    cudaFuncAttributeMaxDynamicSharedMemorySize, GEMM_SMEM);
    cudaFuncSetAttribute(att_kernel, cudaFuncAttributeMaxDynamicSharedMemorySize, ATT_SMEM);

    float *pxq, *pxk, *pxv, *pyq, *pyk, *pyv, *pabar;
    cudaGetSymbolAddress((void**)&pxq, g_xq);
    cudaGetSymbolAddress((void**)&pxk, g_xk);
    cudaGetSymbolAddress((void**)&pxv, g_xv);
    cudaGetSymbolAddress((void**)&pyq, g_yq);
    cudaGetSymbolAddress((void**)&pyk, g_yk);
    cudaGetSymbolAddress((void**)&pyv, g_yv);
    cudaGetSymbolAddress((void**)&pabar, g_abar);

    // idx 0: all three LayerNorms
    ln_all<<<(NTQ + 2 * NTK) / 8, 256>>>(q, k, v, g_q, b_q, g_k, b_k, g_v, b_v);
    // idx 1: k+v projections fused
    gemm_kv<<<2 * (NTK / 128), 256, GEMM_SMEM>>>(pxk, Wk, bk, pyk, pxv, Wv, bv, pyv);
    // idx 2: q projection + saliency epilogue
    gemm_one<<<NTQ / 128, 256, GEMM_SMEM>>>(pxq, Wq, bq, nullptr, pyq, 1);
    // idx 3: attention (prune fused) -- PROFILED SLOT
    att_kernel<<<NHEAD * LWIN, ATTH, ATT_SMEM>>>(logit_bias);
    // idx 4: camera mean
    areduce_kernel<<<(NTO * 128) / 256, 256>>>();
    // idx 5: output projection + skip
    gemm_one<<<NTO / 128, 256, GEMM_SMEM>>>(pabar, Wp, bp, skip, out, 0);
}

// round 17
// speedup vs baseline: 1.2256x; 1.0923x over previous
#include <cuda_runtime.h>
#include <math.h>
#include <stdint.h>

#define FULLMASK 0xffffffffu

#define NCAM  6
#define LWIN  36
#define NHEAD 4
#define DHEAD 32
#define QN    1536
#define KN    384
#define KEEPQ 1152
#define TOPK  96
#define NTQ   55296
#define NTK   13824
#define NTO   9216
#define SCALE 0.17677669529663687f
#define LN_EPS 1e-5f

#define ATTH  512       // 16 warps, 2 rows/warp (R13-proven operating point)
#define NW    16
#define TILE  32

// ---------------- scratch ---------------------------------------------------
__device__ float g_xq[NTQ*128];
__device__ float g_xk[NTK*128];
__device__ float g_xv[NTK*128];
__device__ float g_yq[NTQ*128];
__device__ float g_yk[NTK*128];
__device__ float g_yv[NTK*128];
__device__ float g_sal[NHEAD*LWIN*QN];
__device__ float g_abuf[NHEAD*LWIN*QN*DHEAD];
__device__ float g_abar[NTO*128];

// ---------------- fused LayerNorm for q,k,v (one warp per token) ------------
__global__ __launch_bounds__(256) void ln_all(const float* __restrict__ q,
                                              const float* __restrict__ k,
                                              const float* __restrict__ v,
                                              const float* __restrict__ gq,
                                              const float* __restrict__ bq,
                                              const float* __restrict__ gk,
                                              const float* __restrict__ bk,
                                              const float* __restrict__ gv,
                                              const float* __restrict__ bv)
{
    int w = (blockIdx.x * 256 + threadIdx.x) >> 5;
    int lane = threadIdx.x & 31;
    const float *X, *G, *B;
    float* Y;
    if (w < NTQ) {
        X = q + (size_t)w * 128; Y = g_xq + (size_t)w * 128; G = gq; B = bq;
    } else if (w < NTQ + NTK) {
        int w2 = w - NTQ;
        X = k + (size_t)w2 * 128; Y = g_xk + (size_t)w2 * 128; G = gk; B = bk;
    } else {
        int w2 = w - NTQ - NTK;
        X = v + (size_t)w2 * 128; Y = g_xv + (size_t)w2 * 128; G = gv; B = bv;
    }
    float4 xv = ((const float4*)X)[lane];
    float s  = xv.x + xv.y + xv.z + xv.w;
    float ss = xv.x*xv.x + xv.y*xv.y + xv.z*xv.z + xv.w*xv.w;
    #pragma unroll
    for (int o = 16; o; o >>= 1) {
        s  += __shfl_xor_sync(FULLMASK, s,  o);
        ss += __shfl_xor_sync(FULLMASK, ss, o);
    }
    float mu  = s * (1.f / 128.f);
    float var = ss * (1.f / 128.f) - mu * mu;
    float rs  = rsqrtf(var + LN_EPS);
    float4 gv4 = ((const float4*)G)[lane];
    float4 bv4 = ((const float4*)B)[lane];
    float4 o4;
    o4.x = (xv.x - mu) * rs * gv4.x + bv4.x;
    o4.y = (xv.y - mu) * rs * gv4.y + bv4.y;
    o4.z = (xv.z - mu) * rs * gv4.z + bv4.z;
    o4.w = (xv.w - mu) * rs * gv4.w + bv4.w;
    ((float4*)Y)[lane] = o4;
}

// ---------------- GEMM body (R4-proven) -------------------------------------
#define GCH 32
__device__ __forceinline__ void gemm_body(const float* __restrict__ A,
                                          const float* __restrict__ W,
                                          const float* __restrict__ bias,
                                          const float* __restrict__ skip,
                                          float* __restrict__ C,
                                          size_t mbase, int do_sal, float* smg)
{
    float* As[2] = { smg, smg + 128*33 + 32*128 };
    float* Ws[2] = { smg + 128*33, smg + 2*128*33 + 32*128 };
    int tid = threadIdx.x;
    int ty = tid >> 4, tx = tid & 15;

    float4 pa[4], pw[4];
    #pragma unroll
    for (int r = 0; r < 4; ++r) {
        int i = tid + 256 * r;
        int row = i >> 3, kq = i & 7;
        pa[r] = *(const float4*)(A + (mbase + row) * 128 + kq * 4);
        int kk = i >> 5, c4 = i & 31;
        pw[r] = *(const float4*)(W + (size_t)kk * 128 + c4 * 4);
    }
    #pragma unroll
    for (int r = 0; r < 4; ++r) {
        int i = tid + 256 * r;
        int row = i >> 3, kq = i & 7;
        float* d = &As[0][row * 33 + kq * 4];
        d[0] = pa[r].x; d[1] = pa[r].y; d[2] = pa[r].z; d[3] = pa[r].w;
        int kk = i >> 5, c4 = i & 31;
        *(float4*)&Ws[0][kk * 128 + c4 * 4] = pw[r];
    }
    __syncthreads();

    float acc[8][8];
    #pragma unroll
    for (int i = 0; i < 8; i++)
        #pragma unroll
        for (int j = 0; j < 8; j++) acc[i][j] = 0.f;

    for (int c = 0; c < 4; ++c) {
        int cur = c & 1;
        if (c < 3) {
            #pragma unroll
            for (int r = 0; r < 4; ++r) {
                int i = tid + 256 * r;
                int row = i >> 3, kq = i & 7;
                pa[r] = *(const float4*)(A + (mbase + row) * 128 + (c + 1) * GCH + kq * 4);
                int kk = i >> 5, c4 = i & 31;
                pw[r] = *(const float4*)(W + (size_t)((c + 1) * GCH + kk) * 128 + c4 * 4);
            }
        }
        const float* as = As[cur];
        const float* ws = Ws[cur];
        #pragma unroll 8
        for (int kk = 0; kk < GCH; ++kk) {
            float a[8], bb[8];
            float4 b0 = *(const float4*)&ws[kk * 128 + tx * 8];
            float4 b1 = *(const float4*)&ws[kk * 128 + tx * 8 + 4];
            bb[0]=b0.x; bb[1]=b0.y; bb[2]=b0.z; bb[3]=b0.w;
            bb[4]=b1.x; bb[5]=b1.y; bb[6]=b1.z; bb[7]=b1.w;
            #pragma unroll
            for (int i = 0; i < 8; i++) a[i] = as[(ty * 8 + i) * 33 + kk];
            #pragma unroll
            for (int i = 0; i < 8; i++)
                #pragma unroll
                for (int j = 0; j < 8; j++)
                    acc[i][j] = fmaf(a[i], bb[j], acc[i][j]);
        }
        if (c < 3) {
            int nb = (c + 1) & 1;
            #pragma unroll
            for (int r = 0; r < 4; ++r) {
                int i = tid + 256 * r;
                int row = i >> 3, kq = i & 7;
                float* d = &As[nb][row * 33 + kq * 4];
                d[0] = pa[r].x; d[1] = pa[r].y; d[2] = pa[r].z; d[3] = pa[r].w;
                int kk = i >> 5, c4 = i & 31;
                *(float4*)&Ws[nb][kk * 128 + c4 * 4] = pw[r];
            }
        }
        __syncthreads();
    }

    float4 bi0 = *(const float4*)(bias + tx * 8);
    float4 bi1 = *(const float4*)(bias + tx * 8 + 4);
    #pragma unroll
    for (int i = 0; i < 8; i++) {
        size_t row = mbase + ty * 8 + i;
        float4 o0, o1;
        o0.x = acc[i][0] + bi0.x; o0.y = acc[i][1] + bi0.y;
        o0.z = acc[i][2] + bi0.z; o0.w = acc[i][3] + bi0.w;
        o1.x = acc[i][4] + bi1.x; o1.y = acc[i][5] + bi1.y;
        o1.z = acc[i][6] + bi1.z; o1.w = acc[i][7] + bi1.w;
        if (skip) {
            float4 s0 = *(const float4*)(skip + row * 128 + tx * 8);
            float4 s1 = *(const float4*)(skip + row * 128 + tx * 8 + 4);
            o0.x += s0.x; o0.y += s0.y; o0.z += s0.z; o0.w += s0.w;
            o1.x += s1.x; o1.y += s1.y; o1.z += s1.z; o1.w += s1.w;
        }
        *(float4*)(C + row * 128 + tx * 8)     = o0;
        *(float4*)(C + row * 128 + tx * 8 + 4) = o1;
        if (do_sal) {
            float sv = o0.x*o0.x + o0.y*o0.y + o0.z*o0.z + o0.w*o0.w
                     + o1.x*o1.x + o1.y*o1.y + o1.z*o1.z + o1.w*o1.w;
            sv += __shfl_xor_sync(FULLMASK, sv, 1);
            sv += __shfl_xor_sync(FULLMASK, sv, 2);
            if ((tx & 3) == 0) {
                int h = tx >> 2;
                int r = (int)row;
                int n = r / 9216;
                int rem = r % 9216;
                int l = rem >> 8;
                int w = rem & 255;
                g_sal[(h * LWIN + l) * QN + n * 256 + w] = sv;
            }
        }
    }
}

__global__ __launch_bounds__(256, 2) void gemm_one(const float* __restrict__ A,
                                                   const float* __restrict__ W,
                                                   const float* __restrict__ bias,
                                                   const float* __restrict__ skip,
                                                   float* __restrict__ C, int do_sal)
{
    extern __shared__ float smg[];
    gemm_body(A, W, bias, skip, C, (size_t)blockIdx.x * 128, do_sal, smg);
}

__global__ __launch_bounds__(256, 2) void gemm_kv(const float* __restrict__ Ak,
                                                  const float* __restrict__ Wk,
                                                  const float* __restrict__ bk,
                                                  float* __restrict__ Ck,
                                                  const float* __restrict__ Av,
                                                  const float* __restrict__ Wv,
                                                  const float* __restrict__ bv,
                                                  float* __restrict__ Cv)
{
    extern __shared__ float smg[];
    if (blockIdx.x < NTK / 128)
        gemm_body(Ak, Wk, bk, nullptr, Ck, (size_t)blockIdx.x * 128, 0, smg);
    else
        gemm_body(Av, Wv, bv, nullptr, Cv, (size_t)(blockIdx.x - NTK / 128) * 128, 0, smg);
}

// ---------------- attention -------------------------------------------------
__device__ __forceinline__ float key2float(unsigned k)
{
    return (k & 0x80000000u) ? __uint_as_float(k & 0x7FFFFFFFu)
                             : __uint_as_float(~k);
}

// Exact top-96 thresholds for two rows: 2-bit radix (3 independent REDUXes per
// step -> half the serial depth), early exit when candidates == remaining k.
__device__ __forceinline__ void select2(const unsigned* k0, const unsigned* k1,
                                        unsigned& T0, unsigned& T1)
{
    unsigned p[2] = {0,0};
    int kn[2] = {TOPK,TOPK};
    int rr[2] = {KN,KN};
    bool dn[2] = {false,false};
    unsigned Tt[2] = {0,0};
    const unsigned* kv[2] = {k0, k1};
    #pragma unroll 1
    for (int sh = 30; sh >= 0; sh -= 2) {
        unsigned nm = 0xFFFFFFFFu << sh;
        #pragma unroll
        for (int a = 0; a < 2; ++a) {
            if (dn[a]) continue;
            unsigned t3 = p[a] | (3u << sh);
            unsigned t2 = p[a] | (2u << sh);
            unsigned t1 = p[a] | (1u << sh);
            int c3 = 0, c2 = 0, c1 = 0;
            #pragma unroll
            for (int s = 0; s < 12; s++) {
                unsigned m = kv[a][s] & nm;
                c3 += (m == t3); c2 += (m == t2); c1 += (m == t1);
            }
            c3 = (int)__reduce_add_sync(FULLMASK, (unsigned)c3);
            c2 = (int)__reduce_add_sync(FULLMASK, (unsigned)c2);
            c1 = (int)__reduce_add_sync(FULLMASK, (unsigned)c1);
            unsigned np; int nk, nr;
            if (c3 >= kn[a])                 { np = t3; nk = kn[a];               nr = c3; }
            else if (c3 + c2 >= kn[a])       { np = t2; nk = kn[a] - c3;          nr = c2; }
            else if (c3 + c2 + c1 >= kn[a])  { np = t1; nk = kn[a] - c3 - c2;     nr = c1; }
            else                             { np = p[a]; nk = kn[a] - c3 - c2 - c1;
                                               nr = rr[a] - c3 - c2 - c1; }
            p[a] = np; kn[a] = nk; rr[a] = nr;
            if (nr == nk) {          // every remaining candidate is selected
                unsigned mn = 0xFFFFFFFFu;
                #pragma unroll
                for (int s = 0; s < 12; s++)
                    if ((kv[a][s] & nm) == np) mn = min(mn, kv[a][s]);
                Tt[a] = __reduce_min_sync(FULLMASK, mn);
                dn[a] = true;
            }
        }
        if (dn[0] && dn[1]) break;
    }
    T0 = dn[0] ? Tt[0] : p[0];
    T1 = dn[1] ? Tt[1] : p[1];
}

__device__ __forceinline__ void finish_row(const unsigned* key, unsigned T, int lane,
                                           int rowi, int t_global, int hl,
                                           float2* wjs, const float* Vs)
{
    // three INDEPENDENT warp reductions (pipelined)
    int gq = 0, ce = 0;
    unsigned mx = 0;
    #pragma unroll
    for (int s = 0; s < 12; s++) {
        gq += (key[s] > T);
        ce += (key[s] == T);
        mx = max(mx, key[s]);
    }
    int g   = (int)__reduce_add_sync(FULLMASK, (unsigned)gq);
    int eqc = (int)__reduce_add_sync(FULLMASK, (unsigned)ce);
    mx = __reduce_max_sync(FULLMASK, mx);
    float m = key2float(mx);
    int e_needed = TOPK - g;

    unsigned lmask = (1u << lane) - 1u;
    int kept[12];
    if (eqc == e_needed) {
        // fast path (no straddling ties): keep everything >= T
        #pragma unroll
        for (int s = 0; s < 12; s++) kept[s] = (key[s] >= T);
    } else {
        // exact stable tie-break (rare): serial rank chain
        int eqbase = 0;
        #pragma unroll
        for (int s = 0; s < 12; s++) {
            bool eq = (key[s] == T);
            unsigned bal = __ballot_sync(FULLMASK, eq);
            int rank = eqbase + __popc(bal & lmask);
            eqbase += __popc(bal);
            kept[s] = (key[s] > T) || (eq && rank < e_needed);
        }
    }

    float p[12];
    float sum = 0.f;
    #pragma unroll
    for (int s = 0; s < 12; s++) {
        p[s] = kept[s] ? __expf(key2float(key[s]) - m) : 0.f;
        sum += p[s];
    }
    #pragma unroll
    for (int o = 16; o; o >>= 1) sum += __shfl_xor_sync(FULLMASK, sum, o);
    float inv = 1.f / sum;

    // compaction: 12 INDEPENDENT ballots, then cheap ALU prefix
    unsigned kb[12];
    #pragma unroll
    for (int s = 0; s < 12; s++) kb[s] = __ballot_sync(FULLMASK, kept[s] != 0);
    int run = 0;
    #pragma unroll
    for (int s = 0; s < 12; s++) {
        if (kept[s])
            wjs[rowi * TOPK + run + __popc(kb[s] & lmask)] =
                make_float2(p[s] * inv, __int_as_float(32 * s + lane));
        run += __popc(kb[s]);
    }
    __syncwarp(FULLMASK);

    float accd = 0.f;
    const float4* wj4 = (const float4*)(wjs + rowi * TOPK);
    #pragma unroll 4
    for (int t = 0; t < TOPK / 2; t++) {
        float4 e = wj4[t];
        accd = fmaf(e.x, Vs[__float_as_int(e.y) * 33 + lane], accd);
        accd = fmaf(e.z, Vs[__float_as_int(e.w) * 33 + lane], accd);
    }
    g_abuf[((size_t)hl * QN + t_global) * DHEAD + lane] = accd;
    __syncwarp(FULLMASK);
}

__global__ __launch_bounds__(ATTH, 1) void att_kernel(const float* __restrict__ logit_bias)
{
    extern __shared__ float sm[];
    float*  Ks   = sm;                            // 384*33
    float*  Vs   = Ks + KN * 33;                  // 384*33
    float*  Qs   = Vs + KN * 33;                  // 32*33
    float2* wjs  = (float2*)(Qs + TILE * 33);     // 32*96 float2 (16B aligned)
    int*    list = (int*)(wjs + TILE * TOPK);     // 1152
    float*  uvec = (float*)(list + KEEPQ);        // 32
    __shared__ int hist[256];
    __shared__ int sh_digit, sh_kneed, sh_g, s_cnt;
    __shared__ int wsum[NW];

    int tid = threadIdx.x, lane = tid & 31, wp = tid >> 5;
    int hl = blockIdx.x;
    int h = hl / LWIN, l = hl % LWIN;
    int xx = l / 6, yy = l % 6;

    float lb = 0.f;
    #pragma unroll
    for (int i = 0; i < 6; i++) lb += logit_bias[i];
    lb *= (1.f / 6.f);

    // K,V head slices for this window
    for (int idx = tid; idx < KN * 32; idx += ATTH) {
        int j = idx >> 5, d = idx & 31;
        int n = j >> 6, rem = j & 63;
        int rk = ((n * 6 + xx) * 6 + yy) * 64 + rem;
        Ks[j * 33 + d] = g_yk[(size_t)rk * 128 + h * 32 + d];
        Vs[j * 33 + d] = g_yv[(size_t)rk * 128 + h * 32 + d];
    }
    if (tid == 0) { s_cnt = 0; sh_g = 0; }
    __syncthreads();

    // uniform vector for pruned rows: mean of first 96 V rows
    if (wp == 0) {
        float s = 0.f;
        #pragma unroll 8
        for (int j = 0; j < TOPK; j++) s += Vs[j * 33 + lane];
        uvec[lane] = s * (1.f / TOPK);
    }

    // -------- fused query pruning: exact top-1152 of 1536 (3 keys/thread) ----
    size_t keepbase = (size_t)hl * QN;
    unsigned keys[3];
    #pragma unroll
    for (int i = 0; i < 3; i++) {
        unsigned u = __float_as_uint(g_sal[keepbase + tid + ATTH * i]);
        keys[i] = (u & 0x80000000u) ? ~u : (u | 0x80000000u);
    }
    unsigned prefix = 0;
    int kneed = KEEPQ;
    for (int pass = 3; pass >= 0; --pass) {
        if (tid < 256) hist[tid] = 0;
        __syncthreads();
        int sh = 8 * pass;
        unsigned hm = (pass == 3) ? 0u : (0xFFFFFFFFu << (sh + 8));
        #pragma unroll
        for (int i = 0; i < 3; i++)
            if ((keys[i] & hm) == (prefix & hm))
                atomicAdd(&hist[(keys[i] >> sh) & 255], 1);
        __syncthreads();
        if (tid == 0) {
            int acc = 0, d = 255;
            for (;;) { acc += hist[d]; if (acc >= kneed || d == 0) break; --d; }
            sh_digit = d;
            sh_kneed = kneed - (acc - hist[d]);
        }
        __syncthreads();
        prefix |= ((unsigned)sh_digit) << sh;
        kneed = sh_kneed;
        __syncthreads();
    }
    unsigned T = prefix;
    {
        int lg = 0;
        #pragma unroll
        for (int i = 0; i < 3; i++) lg += (keys[i] > T);
        atomicAdd(&sh_g, lg);
    }
    __syncthreads();
    int e_needed = KEEPQ - sh_g;
    unsigned lmask = (1u << lane) - 1u;
    int rowbase = 0;
    for (int i = 0; i < 3; i++) {
        bool eq = (keys[i] == T);
        unsigned bal = __ballot_sync(FULLMASK, eq);
        if (lane == 0) wsum[wp] = __popc(bal);
        __syncthreads();
        int wpre = 0;
        for (int ww = 0; ww < wp; ++ww) wpre += wsum[ww];
        int rank = rowbase + wpre + __popc(bal & lmask);
        bool keep = (keys[i] > T) || (eq && rank < e_needed);
        int t = tid + ATTH * i;
        if (keep) {
            int pos = atomicAdd(&s_cnt, 1);
            list[pos] = t;
        } else {
            float4* dst = (float4*)(g_abuf + (keepbase + t) * DHEAD);
            const float4* sv = (const float4*)uvec;
            #pragma unroll
            for (int d = 0; d < 8; d++) dst[d] = sv[d];
        }
        int rt = 0;
        for (int ww = 0; ww < NW; ++ww) rt += wsum[ww];
        rowbase += rt;
        __syncthreads();
    }

    // --------------------------- main attention loop --------------------------
    for (int tile = 0; tile < KEEPQ / TILE; ++tile) {
        for (int idx = tid; idx < TILE * 32; idx += ATTH) {
            int qi = idx >> 5, d = idx & 31;
            int t = list[tile * TILE + qi];
            int n = t >> 8, w = t & 255;
            int rq = ((n * 6 + xx) * 6 + yy) * 256 + w;
            Qs[qi * 33 + d] = g_yq[(size_t)rq * 128 + h * 32 + d] * SCALE;
        }
        __syncthreads();

        // logits in registers, 2 rows per warp (R13-proven scalar loop)
        float acc[2][12];
        #pragma unroll
        for (int a = 0; a < 2; a++)
            #pragma unroll
            for (int s = 0; s < 12; s++) acc[a][s] = 0.f;
        #pragma unroll 4
        for (int d = 0; d < 32; ++d) {
            float qv[2];
            #pragma unroll
            for (int a = 0; a < 2; a++) qv[a] = Qs[(2 * wp + a) * 33 + d];
            #pragma unroll
            for (int s = 0; s < 12; s++) {
                float kd = Ks[(32 * s + lane) * 33 + d];
                #pragma unroll
                for (int a = 0; a < 2; a++)
                    acc[a][s] = fmaf(qv[a], kd, acc[a][s]);
            }
        }
        unsigned kk[2][12];
        #pragma unroll
        for (int a = 0; a < 2; a++)
            #pragma unroll
            for (int s = 0; s < 12; s++) {
                unsigned u = __float_as_uint(acc[a][s] + lb);
                kk[a][s] = (u & 0x80000000u) ? ~u : (u | 0x80000000u);
            }

        {
            unsigned T0, T1;
            select2(kk[0], kk[1], T0, T1);
            int rowi0 = 2 * wp;
            int t0 = list[tile * TILE + rowi0];
            int t1 = list[tile * TILE + rowi0 + 1];
            finish_row(kk[0], T0, lane, rowi0,     t0, hl, wjs, Vs);
            finish_row(kk[1], T1, lane, rowi0 + 1, t1, hl, wjs, Vs);
        }
        __syncthreads();
    }
}

// ---------------- mean over cameras into abar -------------------------------
__global__ __launch_bounds__(256) void areduce_kernel()
{
    int idx = blockIdx.x * 256 + threadIdx.x;
    if (idx >= NTO * 128) return;
    int hd = idx & 127, tow = idx >> 7;
    int l = tow >> 8, w = tow & 255;
    int h = hd >> 5, d = hd & 31;
    float s = 0.f;
    #pragma unroll
    for (int n = 0; n < 6; n++)
        s += g_abuf[((size_t)(h * LWIN + l) * QN + n * 256 + w) * DHEAD + d];
    g_abar[idx] = s * (1.f / 6.f);
}

// -------------------------------- launch ------------------------------------
extern "C" void kernel_launch(void* const* d_in, const int* in_sizes, int n_in,
                              void* d_out, int out_size)
{
    const float* q          = (const float*)d_in[0];
    const float* k          = (const float*)d_in[1];
    const float* v          = (const float*)d_in[2];
    const float* skip       = (const float*)d_in[3];
    const float* logit_bias = (const float*)d_in[4];
    const float* g_q        = (const float*)d_in[5];
    const float* b_q        = (const float*)d_in[6];
    const float* g_k        = (const float*)d_in[7];
    const float* b_k        = (const float*)d_in[8];
    const float* g_v        = (const float*)d_in[9];
    const float* b_v        = (const float*)d_in[10];
    const float* Wq         = (const float*)d_in[11];
    const float* bq         = (const float*)d_in[12];
    const float* Wk         = (const float*)d_in[13];
    const float* bk         = (const float*)d_in[14];
    const float* Wv         = (const float*)d_in[15];
    const float* bv         = (const float*)d_in[16];
    const float* Wp         = (const float*)d_in[17];
    const float* bp         = (const float*)d_in[18];
    float* out = (float*)d_out;

    const int GEMM_SMEM = 2 * (128 * 33 + 32 * 128) * 4;   // 66560
    const int ATT_SMEM  = (2 * KN * 33 + TILE * 33 + KEEPQ + 32) * 4
                        + TILE * TOPK * 8;                  // 134912
    cudaFuncSetAttribute(gemm_one,   cudaFuncAttributeMaxDynamicSharedMemorySize, GEMM_SMEM);
    cudaFuncSetAttribute(gemm_kv,    cudaFuncAttributeMaxDynamicSharedMemorySize, GEMM_SMEM);
    cudaFuncSetAttribute(att_kernel, cudaFuncAttributeMaxDynamicSharedMemorySize, ATT_SMEM);

    float *pxq, *pxk, *pxv, *pyq, *pyk, *pyv, *pabar;
    cudaGetSymbolAddress((void**)&pxq, g_xq);
    cudaGetSymbolAddress((void**)&pxk, g_xk);
    cudaGetSymbolAddress((void**)&pxv, g_xv);
    cudaGetSymbolAddress((void**)&pyq, g_yq);
    cudaGetSymbolAddress((void**)&pyk, g_yk);
    cudaGetSymbolAddress((void**)&pyv, g_yv);
    cudaGetSymbolAddress((void**)&pabar, g_abar);

    // idx 0: all three LayerNorms
    ln_all<<<(NTQ + 2 * NTK) / 8, 256>>>(q, k, v, g_q, b_q, g_k, b_k, g_v, b_v);
    // idx 1: k+v projections fused
    gemm_kv<<<2 * (NTK / 128), 256, GEMM_SMEM>>>(pxk, Wk, bk, pyk, pxv, Wv, bv, pyv);
    // idx 2: q projection + saliency epilogue
    gemm_one<<<NTQ / 128, 256, GEMM_SMEM>>>(pxq, Wq, bq, nullptr, pyq, 1);
    // idx 3: attention (prune fused) -- PROFILED SLOT
    att_kernel<<<NHEAD * LWIN, ATTH, ATT_SMEM>>>(logit_bias);
    // idx 4: camera mean
    areduce_kernel<<<(NTO * 128) / 256, 256>>>();
    // idx 5: output projection + skip
    gemm_one<<<NTO / 128, 256, GEMM_SMEM>>>(pabar, Wp, bp, skip, out, 0);
}